// round 5
// baseline (speedup 1.0000x reference)
#include <cuda_runtime.h>

#define Sdim 4096
#define Ddim 64
#define WIN  256
#define Hn   16
#define TQ   32
#define CK   64
#define NCH  9
#define KBUF (CK*NCH)   /* 576 */
#define SROW 580
#define QROW 34

// SMEM floats: scores[TQ][SROW] + Qs[D][QROW] + KVs[CK][D] + invs[TQ]
#define SMEM_FLOATS (TQ*SROW + Ddim*QROW + CK*Ddim + TQ)

__global__ __launch_bounds__(256, 2)
void swa_kernel(const float* __restrict__ Q, const float* __restrict__ K,
                const float* __restrict__ V, float* __restrict__ outp,
                float* __restrict__ attn)
{
    extern __shared__ float sm[];
    float* scores = sm;                     // [TQ][SROW]
    float* Qs     = sm + TQ*SROW;           // [D][QROW]  (d-major)
    float* KVs    = Qs + Ddim*QROW;         // [CK][D] or [D][CK]
    float* invs   = KVs + CK*Ddim;          // [TQ]

    const int h    = blockIdx.y;
    const int qb   = blockIdx.x * TQ;
    const int tid  = threadIdx.x;
    const int koff = qb - WIN;              // buffer covers keys [koff, koff+576)

    // ---- Load Q tile (32x64), store transposed d-major ----
    {
        const float4* Q4 = (const float4*)(Q + (size_t)(h*Sdim + qb)*Ddim);
        #pragma unroll
        for (int i = 0; i < 2; i++) {
            int idx = tid + 256*i;      // 512 float4 total
            int q  = idx >> 4;
            int dg = idx & 15;
            float4 v = Q4[q*16 + dg];
            Qs[(4*dg+0)*QROW + q] = v.x;
            Qs[(4*dg+1)*QROW + q] = v.y;
            Qs[(4*dg+2)*QROW + q] = v.z;
            Qs[(4*dg+3)*QROW + q] = v.w;
        }
    }
    __syncthreads();

    const int tq = tid & 15;    // 16 query-pairs / 16 query-splits
    const int tk = tid >> 4;    // 16 groups of 4 keys / 4 dims

    // ======== GEMM1: scores = Q K^T * 0.125, banded mask -> -1e9 ========
    for (int c = 0; c < NCH; c++) {
        const int kc = koff + c*CK;
        const bool any = (kc < Sdim) && (kc + CK > 0);   // uniform per block
        if (any) {
            // load K chunk transposed: KVs[d][k], stride CK
            #pragma unroll
            for (int i = 0; i < 4; i++) {
                int idx = tid + 256*i;   // 1024 float4
                int kk = idx >> 4;
                int dg = idx & 15;
                int kg = kc + kk;
                float4 v = make_float4(0.f,0.f,0.f,0.f);
                if (kg >= 0 && kg < Sdim)
                    v = *(const float4*)(K + (size_t)(h*Sdim + kg)*Ddim + 4*dg);
                KVs[(4*dg+0)*CK + kk] = v.x;
                KVs[(4*dg+1)*CK + kk] = v.y;
                KVs[(4*dg+2)*CK + kk] = v.z;
                KVs[(4*dg+3)*CK + kk] = v.w;
            }
            __syncthreads();

            float acc[2][4] = {};
            #pragma unroll 8
            for (int d = 0; d < Ddim; d++) {
                float2 qv = *(const float2*)&Qs[d*QROW + 2*tq];
                float4 kv = *(const float4*)&KVs[d*CK + 4*tk];
                acc[0][0] += qv.x*kv.x; acc[0][1] += qv.x*kv.y;
                acc[0][2] += qv.x*kv.z; acc[0][3] += qv.x*kv.w;
                acc[1][0] += qv.y*kv.x; acc[1][1] += qv.y*kv.y;
                acc[1][2] += qv.y*kv.z; acc[1][3] += qv.y*kv.w;
            }
            #pragma unroll
            for (int j = 0; j < 2; j++) {
                int q  = 2*tq + j;
                int qg = qb + q;
                int k0 = kc + 4*tk;
                float4 r;
                float* rp = &r.x;
                #pragma unroll
                for (int i = 0; i < 4; i++) {
                    int kg = k0 + i;
                    bool ok = (kg >= 0) && (kg < Sdim) &&
                              ((unsigned)(kg - qg + WIN) <= 2u*WIN);
                    rp[i] = ok ? acc[j][i]*0.125f : -1e9f;
                }
                *(float4*)&scores[q*SROW + c*CK + 4*tk] = r;
            }
            __syncthreads();   // KVs reused next chunk
        } else {
            float4 mneg = make_float4(-1e9f,-1e9f,-1e9f,-1e9f);
            *(float4*)&scores[(2*tq  )*SROW + c*CK + 4*tk] = mneg;
            *(float4*)&scores[(2*tq+1)*SROW + c*CK + 4*tk] = mneg;
        }
    }
    __syncthreads();

    // ======== softmax per query row (warp handles 4 rows) ========
    {
        const int warp = tid >> 5, lane = tid & 31;
        for (int qq = 0; qq < 4; qq++) {
            int q = warp*4 + qq;
            float* row = scores + q*SROW;
            float m = -3.0e38f;
            for (int i = lane; i < KBUF; i += 32) m = fmaxf(m, row[i]);
            #pragma unroll
            for (int o = 16; o > 0; o >>= 1) m = fmaxf(m, __shfl_xor_sync(0xffffffffu, m, o));
            float ssum = 0.f;
            for (int i = lane; i < KBUF; i += 32) {
                float p = __expf(row[i] - m);   // masked -1e9 underflows to exact 0
                row[i] = p;
                ssum += p;
            }
            #pragma unroll
            for (int o = 16; o > 0; o >>= 1) ssum += __shfl_xor_sync(0xffffffffu, ssum, o);
            if (lane == 0) invs[q] = 1.0f / ssum;
        }
    }
    __syncthreads();

    // ======== write dense attn rows (zeros outside buffer/band) ========
    {
        float* arow = attn + (size_t)(h*Sdim + qb)*Sdim;
        for (int idx = tid; idx < TQ*(Sdim/4); idx += 256) {
            int q  = idx >> 10;            // Sdim/4 = 1024 groups per row
            int g  = idx & 1023;
            int k0 = g*4;
            int b  = k0 - koff;
            float4 v;
            if (b >= 0 && b < KBUF) {
                float4 p = *(float4*)&scores[q*SROW + b];
                float is = invs[q];
                v = make_float4(p.x*is, p.y*is, p.z*is, p.w*is);
            } else {
                v = make_float4(0.f,0.f,0.f,0.f);
            }
            *(float4*)&arow[(size_t)q*Sdim + k0] = v;
        }
    }

    // ======== GEMM2: out = P V (P = unnormalized exp, scale at end) ========
    float acc[2][4] = {};
    for (int c = 0; c < NCH; c++) {
        const int kc = koff + c*CK;
        if (kc >= Sdim || kc + CK <= 0) continue;   // uniform
        // load V chunk (k-major, stride D)
        #pragma unroll
        for (int i = 0; i < 4; i++) {
            int idx = tid + 256*i;
            int kk = idx >> 4;
            int dg = idx & 15;
            int kg = kc + kk;
            float4 v = make_float4(0.f,0.f,0.f,0.f);
            if (kg >= 0 && kg < Sdim)
                v = *(const float4*)(V + (size_t)(h*Sdim + kg)*Ddim + 4*dg);
            *(float4*)&KVs[kk*Ddim + 4*dg] = v;
        }
        __syncthreads();

        const int cb = c*CK;
        #pragma unroll 8
        for (int kk = 0; kk < CK; kk++) {
            float pa = scores[(tq     )*SROW + cb + kk];
            float pb = scores[(tq + 16)*SROW + cb + kk];
            float4 vv = *(const float4*)&KVs[kk*Ddim + 4*tk];
            acc[0][0] += pa*vv.x; acc[0][1] += pa*vv.y;
            acc[0][2] += pa*vv.z; acc[0][3] += pa*vv.w;
            acc[1][0] += pb*vv.x; acc[1][1] += pb*vv.y;
            acc[1][2] += pb*vv.z; acc[1][3] += pb*vv.w;
        }
        __syncthreads();
    }

    // ======== write out tile ========
    {
        float* orow = outp + (size_t)(h*Sdim + qb)*Ddim;
        #pragma unroll
        for (int j = 0; j < 2; j++) {
            int q = tq + 16*j;
            float is = invs[q];
            float4 r = make_float4(acc[j][0]*is, acc[j][1]*is,
                                   acc[j][2]*is, acc[j][3]*is);
            *(float4*)&orow[q*Ddim + 4*tk] = r;
        }
    }
}

extern "C" void kernel_launch(void* const* d_in, const int* in_sizes, int n_in,
                              void* d_out, int out_size) {
    const float* Q = (const float*)d_in[0];
    const float* K = (const float*)d_in[1];
    const float* V = (const float*)d_in[2];
    float* outp = (float*)d_out;
    float* attn = outp + (size_t)Hn*Sdim*Ddim;   // tuple: (out, attn)

    const int smem_bytes = SMEM_FLOATS * (int)sizeof(float);   // ~97 KB
    cudaFuncSetAttribute(swa_kernel, cudaFuncAttributeMaxDynamicSharedMemorySize,
                         smem_bytes);

    dim3 grid(Sdim / TQ, Hn);   // (128, 16)
    swa_kernel<<<grid, 256, smem_bytes>>>(Q, K, V, outp, attn);
}

// round 6
// speedup vs baseline: 1.1982x; 1.1982x over previous
#include <cuda_runtime.h>

#define Sdim 4096
#define Ddim 64
#define WIN  256
#define Hn   16
#define TQ   64
#define CK   128
#define NCH  5
#define KBUF 640
#define SROW 644
#define QROW 68
#define NT   512

#define SM_QS   (TQ*SROW)             /* 41216 */
#define SM_KV   (SM_QS + Ddim*QROW)   /* 45568 */
#define SM_INV  (SM_KV + CK*Ddim)     /* 53760 */
#define SMEM_FLOATS (SM_INV + TQ)     /* 53824 floats = 215296 B */

typedef unsigned long long u64;

__device__ __forceinline__ u64 pk2(float v) {
    u64 r; asm("mov.b64 %0,{%1,%1};" : "=l"(r) : "f"(v)); return r;
}
__device__ __forceinline__ void fma2(u64 &d, u64 a, u64 b) {
    asm("fma.rn.f32x2 %0,%1,%2,%0;" : "+l"(d) : "l"(a), "l"(b));
}
__device__ __forceinline__ float2 upk2(u64 v) {
    float2 f; asm("mov.b64 {%0,%1},%2;" : "=f"(f.x), "=f"(f.y) : "l"(v)); return f;
}

#define SWZ(d) ((((d) >> 2) & 7) << 2)

__global__ __launch_bounds__(NT, 1)
void swa_kernel(const float* __restrict__ Q, const float* __restrict__ K,
                const float* __restrict__ V, float* __restrict__ outp,
                float* __restrict__ attn)
{
    extern __shared__ float sm[];
    float* scores = sm;                 // [64][SROW]  scores -> P
    float* Qs     = sm + SM_QS;         // [64][QROW]  d-major, pre-scaled 0.125
    float* KV     = sm + SM_KV;         // K: [d][128] swizzled / V: [k][64]
    float* invs   = sm + SM_INV;        // [64]

    const int h    = blockIdx.y;
    const int qb   = blockIdx.x * TQ;
    const int tid  = threadIdx.x;
    const int koff = qb - WIN;          // buffer covers keys [koff, koff+640)

    // ---- Q load: transpose d-major, fold in 1/8 ----
    {
        const float4* Q4 = (const float4*)(Q + (size_t)(h*Sdim + qb)*Ddim);
        #pragma unroll
        for (int i = 0; i < 2; i++) {
            int idx = tid + NT*i;            // 1024 float4
            int q = idx >> 4, dg = idx & 15;
            float4 v = Q4[idx];
            Qs[(4*dg+0)*QROW + q] = v.x * 0.125f;
            Qs[(4*dg+1)*QROW + q] = v.y * 0.125f;
            Qs[(4*dg+2)*QROW + q] = v.z * 0.125f;
            Qs[(4*dg+3)*QROW + q] = v.w * 0.125f;
        }
    }

    const int warp = tid >> 5, lane = tid & 31;
    const int g1_q0 = warp << 2;            // warp owns 4 q-rows
    const int g1_k0 = lane << 2;            // lane owns 4 k-cols (of 128)

    // ======== GEMM1: scores = (Q/8)K^T, band mask -> -1e9 ========
    for (int c = 0; c < NCH; c++) {
        const int kc = koff + c*CK;
        if (kc >= Sdim || kc + CK <= 0) {   // uniform: fully OOB
            float4 mneg = make_float4(-1e9f,-1e9f,-1e9f,-1e9f);
            #pragma unroll
            for (int j = 0; j < 4; j++)
                *(float4*)&scores[(g1_q0+j)*SROW + c*CK + g1_k0] = mneg;
            continue;
        }
        __syncthreads();                    // KV free (prev readers done)
        #pragma unroll
        for (int i = 0; i < 4; i++) {       // K chunk -> transposed swizzled
            int idx = tid + NT*i;           // 2048 float4
            int kk = idx >> 4, dg = idx & 15;
            int kg = kc + kk;
            float4 v = make_float4(0.f,0.f,0.f,0.f);
            if ((unsigned)kg < Sdim)
                v = *(const float4*)(K + (size_t)(h*Sdim + kg)*Ddim + 4*dg);
            int kk4 = kk & ~3, kr = kk & 3, d0 = 4*dg;
            KV[((d0+0)<<7) + ((kk4 ^ SWZ(d0+0)) | kr)] = v.x;
            KV[((d0+1)<<7) + ((kk4 ^ SWZ(d0+1)) | kr)] = v.y;
            KV[((d0+2)<<7) + ((kk4 ^ SWZ(d0+2)) | kr)] = v.z;
            KV[((d0+3)<<7) + ((kk4 ^ SWZ(d0+3)) | kr)] = v.w;
        }
        __syncthreads();

        u64 acc[4][2];
        #pragma unroll
        for (int j = 0; j < 4; j++) { acc[j][0] = 0ULL; acc[j][1] = 0ULL; }

        #pragma unroll 8
        for (int d = 0; d < Ddim; d++) {
            float4 qv = *(const float4*)(Qs + d*QROW + g1_q0);   // broadcast
            ulonglong2 kv = *(const ulonglong2*)(KV + (d<<7) + (g1_k0 ^ SWZ(d)));
            u64 a;
            a = pk2(qv.x); fma2(acc[0][0], a, kv.x); fma2(acc[0][1], a, kv.y);
            a = pk2(qv.y); fma2(acc[1][0], a, kv.x); fma2(acc[1][1], a, kv.y);
            a = pk2(qv.z); fma2(acc[2][0], a, kv.x); fma2(acc[2][1], a, kv.y);
            a = pk2(qv.w); fma2(acc[3][0], a, kv.x); fma2(acc[3][1], a, kv.y);
        }

        const int kg0 = kc + g1_k0;
        #pragma unroll
        for (int j = 0; j < 4; j++) {
            int qg = qb + g1_q0 + j;
            float2 a0 = upk2(acc[j][0]), a1 = upk2(acc[j][1]);
            float4 r;
            r.x = ((unsigned)(kg0+0) < Sdim && (unsigned)(kg0+0 - qg + WIN) <= 2u*WIN) ? a0.x : -1e9f;
            r.y = ((unsigned)(kg0+1) < Sdim && (unsigned)(kg0+1 - qg + WIN) <= 2u*WIN) ? a0.y : -1e9f;
            r.z = ((unsigned)(kg0+2) < Sdim && (unsigned)(kg0+2 - qg + WIN) <= 2u*WIN) ? a1.x : -1e9f;
            r.w = ((unsigned)(kg0+3) < Sdim && (unsigned)(kg0+3 - qg + WIN) <= 2u*WIN) ? a1.y : -1e9f;
            *(float4*)&scores[(g1_q0+j)*SROW + c*CK + g1_k0] = r;
        }
    }
    __syncthreads();

    // ======== softmax: warp w owns rows 4w..4w+3 (640 cols) ========
    #pragma unroll
    for (int r = 0; r < 4; r++) {
        float* row = scores + (warp*4 + r)*SROW;
        float4 vals[5];
        float m = -3.0e38f;
        #pragma unroll
        for (int it = 0; it < 5; it++) {
            vals[it] = *(const float4*)(row + ((it*32 + lane) << 2));
            m = fmaxf(m, fmaxf(fmaxf(vals[it].x, vals[it].y), fmaxf(vals[it].z, vals[it].w)));
        }
        #pragma unroll
        for (int o = 16; o > 0; o >>= 1) m = fmaxf(m, __shfl_xor_sync(~0u, m, o));
        float s = 0.f;
        #pragma unroll
        for (int it = 0; it < 5; it++) {
            float4 v = vals[it];
            v.x = __expf(v.x - m); v.y = __expf(v.y - m);
            v.z = __expf(v.z - m); v.w = __expf(v.w - m);
            s += (v.x + v.y) + (v.z + v.w);
            *(float4*)(row + ((it*32 + lane) << 2)) = v;
        }
        #pragma unroll
        for (int o = 16; o > 0; o >>= 1) s += __shfl_xor_sync(~0u, s, o);
        if (lane == 0) invs[warp*4 + r] = 1.0f / s;
    }
    __syncthreads();

    // ======== dense attn write (streaming stores) ========
    {
        float* abase = attn + (size_t)(h*Sdim + qb)*Sdim;
        #pragma unroll 4
        for (int it = 0; it < 128; it++) {
            int idx = tid + NT*it;
            int q = idx >> 10, k0 = (idx & 1023) << 2;
            int b = k0 - koff;
            float4 v = make_float4(0.f,0.f,0.f,0.f);
            if ((unsigned)b < KBUF) {
                float4 p = *(const float4*)(scores + q*SROW + b);
                float iv = invs[q];
                v = make_float4(p.x*iv, p.y*iv, p.z*iv, p.w*iv);
            }
            __stcs((float4*)(abase + ((size_t)q << 12) + k0), v);
        }
    }

    // ======== GEMM2: out = P V, k-split-2 ========
    const int ksp = tid >> 8;           // which k-half
    const int t   = tid & 255;
    const int q0  = (t >> 4) << 2;      // 0..60
    const int d0  = (t & 15) << 2;      // 0..60

    u64 acc[4][2];
    #pragma unroll
    for (int j = 0; j < 4; j++) { acc[j][0] = 0ULL; acc[j][1] = 0ULL; }

    for (int c = 0; c < NCH; c++) {
        const int kc = koff + c*CK;
        if (kc >= Sdim || kc + CK <= 0) continue;   // P exactly 0 there
        __syncthreads();                             // prev KV readers done
        #pragma unroll
        for (int i = 0; i < 4; i++) {               // V chunk [k][64]
            int idx = tid + NT*i;
            int kk = idx >> 4, dg = idx & 15;
            int kg = kc + kk;
            float4 v = make_float4(0.f,0.f,0.f,0.f);
            if ((unsigned)kg < Sdim)
                v = *(const float4*)(V + (size_t)(h*Sdim + kg)*Ddim + 4*dg);
            *(float4*)&KV[(kk << 6) + 4*dg] = v;
        }
        __syncthreads();

        const float* srow = scores + c*CK;
        #pragma unroll 4
        for (int kb = ksp*64; kb < ksp*64 + 64; kb += 4) {
            float4 p0 = *(const float4*)(srow + (q0+0)*SROW + kb);
            float4 p1 = *(const float4*)(srow + (q0+1)*SROW + kb);
            float4 p2 = *(const float4*)(srow + (q0+2)*SROW + kb);
            float4 p3 = *(const float4*)(srow + (q0+3)*SROW + kb);
            #pragma unroll
            for (int i = 0; i < 4; i++) {
                ulonglong2 vv = *(const ulonglong2*)(KV + ((kb+i) << 6) + d0);
                const float* pf0 = &p0.x; const float* pf1 = &p1.x;
                const float* pf2 = &p2.x; const float* pf3 = &p3.x;
                u64 a;
                a = pk2(pf0[i]); fma2(acc[0][0], a, vv.x); fma2(acc[0][1], a, vv.y);
                a = pk2(pf1[i]); fma2(acc[1][0], a, vv.x); fma2(acc[1][1], a, vv.y);
                a = pk2(pf2[i]); fma2(acc[2][0], a, vv.x); fma2(acc[2][1], a, vv.y);
                a = pk2(pf3[i]); fma2(acc[3][0], a, vv.x); fma2(acc[3][1], a, vv.y);
            }
        }
    }

    // ======== cross-half reduction + output ========
    __syncthreads();
    float* red = sm + SM_QS;            // 4096 floats (Qs dead)
    if (ksp == 1) {
        #pragma unroll
        for (int j = 0; j < 4; j++) {
            float2 f0 = upk2(acc[j][0]), f1 = upk2(acc[j][1]);
            *(float4*)&red[(t*4 + j)*4] = make_float4(f0.x, f0.y, f1.x, f1.y);
        }
    }
    __syncthreads();
    if (ksp == 0) {
        float* obase = outp + (size_t)(h*Sdim + qb)*Ddim;
        #pragma unroll
        for (int j = 0; j < 4; j++) {
            float2 f0 = upk2(acc[j][0]), f1 = upk2(acc[j][1]);
            float4 o = *(const float4*)&red[(t*4 + j)*4];
            float iv = invs[q0 + j];
            o.x = (o.x + f0.x) * iv;
            o.y = (o.y + f0.y) * iv;
            o.z = (o.z + f1.x) * iv;
            o.w = (o.w + f1.y) * iv;
            __stcs((float4*)(obase + (size_t)(q0 + j)*Ddim + d0), o);
        }
    }
}

extern "C" void kernel_launch(void* const* d_in, const int* in_sizes, int n_in,
                              void* d_out, int out_size) {
    const float* Q = (const float*)d_in[0];
    const float* K = (const float*)d_in[1];
    const float* V = (const float*)d_in[2];
    float* outp = (float*)d_out;
    float* attn = outp + (size_t)Hn*Sdim*Ddim;      // tuple: (out, attn)

    const int smem_bytes = SMEM_FLOATS * (int)sizeof(float);  // 215296
    cudaFuncSetAttribute(swa_kernel, cudaFuncAttributeMaxDynamicSharedMemorySize,
                         smem_bytes);
    dim3 grid(Sdim / TQ, Hn);                        // (64, 16)
    swa_kernel<<<grid, NT, smem_bytes>>>(Q, K, V, outp, attn);
}